// round 2
// baseline (speedup 1.0000x reference)
#include <cuda_runtime.h>

#define N_NODES 1000000
#define DEGREE 31
#define BLOCK 256
#define THRESH 16

__device__ float  g_p[N_NODES];
__device__ double g_sum;
__device__ int    g_is64;

// Kernel 0: detect index dtype. If the buffer is int64, every hi-word of the
// first 32 elements is 0 (indices < 2^20). If int32, those words are random
// indices in [0, 1e6) -> P(all zero) ~ 0.
__global__ void detect_kernel(const int* __restrict__ nb_raw) {
    int lane = threadIdx.x;                 // 32 threads
    int hi = nb_raw[lane * 2 + 1];
    unsigned all0 = __ballot_sync(0xffffffffu, hi == 0);
    if (lane == 0) {
        g_is64 = (all0 == 0xffffffffu) ? 1 : 0;
        g_sum = 0.0;
    }
}

// Kernel 1: p = sigmoid(gains).
__global__ void __launch_bounds__(BLOCK) sigmoid_kernel(const float* __restrict__ gains) {
    int i = blockIdx.x * BLOCK + threadIdx.x;
    if (i < N_NODES) {
        float x = gains[i];
        g_p[i] = 1.0f / (1.0f + __expf(-x));
    }
}

// Kernel 2: per-node Poisson-binomial DP with absorbing state at THRESH.
__global__ void __launch_bounds__(BLOCK) dp_kernel(const void* __restrict__ neighbors) {
    __shared__ int   sidx[BLOCK * DEGREE];
    __shared__ float sred[BLOCK / 32];

    const int tid = threadIdx.x;
    const long long blockStart = (long long)blockIdx.x * BLOCK;
    const int count = (int)min((long long)BLOCK, (long long)N_NODES - blockStart);
    const int total = count * DEGREE;
    const long long elemBase = blockStart * (long long)DEGREE;

    // Coalesced staging of this block's neighbor rows -> int32 in smem.
    if (g_is64) {
        const long long* nb = (const long long*)neighbors + elemBase;
        for (int t = tid; t < total; t += BLOCK)
            sidx[t] = (int)nb[t];
    } else {
        const int* nb = (const int*)neighbors + elemBase;
        for (int t = tid; t < total; t += BLOCK)
            sidx[t] = nb[t];
    }
    __syncthreads();

    float contrib = 0.0f;
    if (tid < count) {
        const int node = (int)(blockStart + tid);

        // Gather the 32 group probabilities (31 independent L2-resident loads).
        float pv[DEGREE + 1];
        pv[0] = g_p[node];
        #pragma unroll
        for (int j = 0; j < DEGREE; j++) {
            int idx = sidx[tid * DEGREE + j];
            idx = min(max(idx, 0), N_NODES - 1);   // crash-proofing
            pv[j + 1] = __ldg(&g_p[idx]);
        }

        // dp[k] = P(exactly k successes) for k<16; dp[16] = P(>=16) (absorbing).
        float dp[THRESH + 1];
        dp[0] = 1.0f;
        #pragma unroll
        for (int k = 1; k <= THRESH; k++) dp[k] = 0.0f;

        #pragma unroll
        for (int j = 0; j < DEGREE + 1; j++) {
            const float pj = pv[j];
            const int kmax = (j + 1 < THRESH) ? (j + 1) : THRESH;  // triangular prune
            if (kmax == THRESH)
                dp[THRESH] = fmaf(pj, dp[THRESH - 1], dp[THRESH]); // absorb
            #pragma unroll
            for (int k = THRESH - 1; k >= 1; k--)
                if (k <= kmax)
                    dp[k] = fmaf(pj, dp[k - 1] - dp[k], dp[k]);
            dp[0] = dp[0] * (1.0f - pj);
        }
        contrib = dp[THRESH] - 0.25f * pv[0];
    }

    // Warp reduce, then block reduce, one double atomic per block.
    #pragma unroll
    for (int o = 16; o; o >>= 1)
        contrib += __shfl_down_sync(0xffffffffu, contrib, o);
    if ((tid & 31) == 0) sred[tid >> 5] = contrib;
    __syncthreads();
    if (tid < 32) {
        float v = (tid < BLOCK / 32) ? sred[tid] : 0.0f;
        #pragma unroll
        for (int o = 4; o; o >>= 1)
            v += __shfl_down_sync(0xffffffffu, v, o);
        if (tid == 0) atomicAdd(&g_sum, (double)v);
    }
}

// Kernel 3: write the negated loss.
__global__ void finalize_kernel(float* __restrict__ out) {
    out[0] = -(float)g_sum;
}

extern "C" void kernel_launch(void* const* d_in, const int* in_sizes, int n_in,
                              void* d_out, int out_size) {
    // Resolve input order from element counts (gains: 1M, neighbors: 31M).
    int gi = 0, ni = 1;
    if (in_sizes[0] != N_NODES) { gi = 1; ni = 0; }
    const float* gains     = (const float*)d_in[gi];
    const void*  neighbors = d_in[ni];
    float*       out       = (float*)d_out;

    const int nblk = (N_NODES + BLOCK - 1) / BLOCK;
    detect_kernel<<<1, 32>>>((const int*)neighbors);
    sigmoid_kernel<<<nblk, BLOCK>>>(gains);
    dp_kernel<<<nblk, BLOCK>>>(neighbors);
    finalize_kernel<<<1, 1>>>(out);
}

// round 3
// speedup vs baseline: 1.7861x; 1.7861x over previous
#include <cuda_runtime.h>

#define N_NODES 1000000
#define DEGREE 31
#define BLOCK 256
#define THRESH 16

__device__ float  g_p[N_NODES];
__device__ double g_sum;
__device__ int    g_is64;
__device__ unsigned int g_done = 0;

// Kernel 1: p = sigmoid(gains). Block 0 warp 0 also detects index dtype and
// zeroes the accumulator.
__global__ void __launch_bounds__(BLOCK) prep_kernel(const float* __restrict__ gains,
                                                     const int* __restrict__ nb_raw) {
    int i = blockIdx.x * BLOCK + threadIdx.x;
    if (blockIdx.x == 0 && threadIdx.x < 32) {
        // If int64, hi-words of the first 32 elements are all 0 (indices < 2^20).
        // If int32, those words are random indices in [0, 1e6): P(all 0) ~ 0.
        int hi = nb_raw[threadIdx.x * 2 + 1];
        unsigned all0 = __ballot_sync(0xffffffffu, hi == 0);
        if (threadIdx.x == 0) {
            g_is64 = (all0 == 0xffffffffu) ? 1 : 0;
            g_sum = 0.0;
        }
    }
    if (i < N_NODES) {
        float x = gains[i];
        g_p[i] = 1.0f / (1.0f + __expf(-x));
    }
}

// Per-thread Poisson-binomial DP with absorbing state at THRESH.
__device__ __forceinline__ float dp_node(const float* __restrict__ pv) {
    float dp[THRESH + 1];
    dp[0] = 1.0f;
    #pragma unroll
    for (int k = 1; k <= THRESH; k++) dp[k] = 0.0f;

    #pragma unroll
    for (int j = 0; j < DEGREE + 1; j++) {
        const float pj = pv[j];
        const int kmax = (j + 1 < THRESH) ? (j + 1) : THRESH;  // triangular prune
        if (kmax == THRESH)
            dp[THRESH] = fmaf(pj, dp[THRESH - 1], dp[THRESH]); // absorbing state
        #pragma unroll
        for (int k = THRESH - 1; k >= 1; k--)
            if (k <= kmax)
                dp[k] = fmaf(pj, dp[k - 1] - dp[k], dp[k]);
        dp[0] = dp[0] * (1.0f - pj);
    }
    return dp[THRESH];
}

// Kernel 2: stage indices coalesced -> smem, gather p, run DP, reduce.
// Last block writes the final negated loss.
__global__ void __launch_bounds__(BLOCK) dp_kernel(const void* __restrict__ neighbors,
                                                   float* __restrict__ out,
                                                   int nblk) {
    __shared__ int   sidx[BLOCK * DEGREE];
    __shared__ float sred[BLOCK / 32];

    const int tid = threadIdx.x;
    const long long blockStart = (long long)blockIdx.x * BLOCK;
    const int count = (int)min((long long)BLOCK, (long long)N_NODES - blockStart);
    const long long elemBase = blockStart * (long long)DEGREE;

    // Coalesced, vectorized staging of this block's neighbor rows into smem.
    if (g_is64) {
        // int64 path: int4 = two indices (low words at .x and .z).
        const int4* nb4 = (const int4*)((const long long*)neighbors + elemBase);
        if (count == BLOCK) {
            #pragma unroll 4
            for (int t = tid; t < BLOCK * DEGREE / 2; t += BLOCK) {
                int4 v = nb4[t];
                sidx[2 * t]     = v.x;
                sidx[2 * t + 1] = v.z;
            }
        } else {
            for (int t = tid; t < count * DEGREE / 2; t += BLOCK) {
                int4 v = nb4[t];
                sidx[2 * t]     = v.x;
                sidx[2 * t + 1] = v.z;
            }
            // count*DEGREE is even for all real block sizes here (256 or 64).
        }
    } else {
        // int32 path: int4 = four indices.
        const int4* nb4 = (const int4*)((const int*)neighbors + elemBase);
        if (count == BLOCK) {
            #pragma unroll 4
            for (int t = tid; t < BLOCK * DEGREE / 4; t += BLOCK) {
                int4 v = nb4[t];
                sidx[4 * t]     = v.x;
                sidx[4 * t + 1] = v.y;
                sidx[4 * t + 2] = v.z;
                sidx[4 * t + 3] = v.w;
            }
        } else {
            int tot = count * DEGREE;
            for (int t = tid; t < tot / 4; t += BLOCK) {
                int4 v = nb4[t];
                sidx[4 * t]     = v.x;
                sidx[4 * t + 1] = v.y;
                sidx[4 * t + 2] = v.z;
                sidx[4 * t + 3] = v.w;
            }
            for (int t = (tot / 4) * 4 + tid; t < tot; t += BLOCK)
                sidx[t] = ((const int*)neighbors)[elemBase + t];
        }
    }
    __syncthreads();

    float contrib = 0.0f;
    if (tid < count) {
        const int node = (int)(blockStart + tid);
        float pv[DEGREE + 1];
        pv[0] = g_p[node];
        #pragma unroll
        for (int j = 0; j < DEGREE; j++) {
            int idx = sidx[tid * DEGREE + j];
            idx = min(max(idx, 0), N_NODES - 1);   // crash-proofing
            pv[j + 1] = __ldg(&g_p[idx]);
        }
        contrib = dp_node(pv) - 0.25f * pv[0];
    }

    // Warp reduce -> block reduce -> one double atomic per block.
    #pragma unroll
    for (int o = 16; o; o >>= 1)
        contrib += __shfl_down_sync(0xffffffffu, contrib, o);
    if ((tid & 31) == 0) sred[tid >> 5] = contrib;
    __syncthreads();
    if (tid < 32) {
        float v = (tid < BLOCK / 32) ? sred[tid] : 0.0f;
        #pragma unroll
        for (int o = 4; o; o >>= 1)
            v += __shfl_down_sync(0xffffffffu, v, o);
        if (tid == 0) {
            atomicAdd(&g_sum, (double)v);
            __threadfence();
            unsigned int done = atomicAdd(&g_done, 1u);
            if (done == (unsigned)nblk - 1u) {
                // All blocks' g_sum contributions are visible (fence + counter).
                double s = atomicAdd(&g_sum, 0.0);   // L2-coherent read
                out[0] = -(float)s;
                g_done = 0;                           // reset for next replay
            }
        }
    }
}

extern "C" void kernel_launch(void* const* d_in, const int* in_sizes, int n_in,
                              void* d_out, int out_size) {
    // Resolve input order from element counts (gains: 1M, neighbors: 31M).
    int gi = 0, ni = 1;
    if (in_sizes[0] != N_NODES) { gi = 1; ni = 0; }
    const float* gains     = (const float*)d_in[gi];
    const void*  neighbors = d_in[ni];
    float*       out       = (float*)d_out;

    const int nblk = (N_NODES + BLOCK - 1) / BLOCK;
    prep_kernel<<<nblk, BLOCK>>>(gains, (const int*)neighbors);
    dp_kernel<<<nblk, BLOCK>>>(neighbors, out, nblk);
}